// round 1
// baseline (speedup 1.0000x reference)
#include <cuda_runtime.h>
#include <stdint.h>

// out = (x @ W_v + b_v) @ W_out + b_out, because the eye() mask makes the
// softmax exactly one-hot => attn@v == v. We precompute W_comb = W_v@W_out
// and b_comb = b_v@W_out + b_out, then run one big TF32 tensor-core GEMM.

#define CDIM 768
#define BM 128
#define BN 128
#define BK 16
#define NTHREADS 256

// scratch (no allocations allowed in kernel_launch)
__device__ float g_Wc[CDIM * CDIM];
__device__ float g_bc[CDIM];

__device__ __forceinline__ float f2tf32(float x) {
    uint32_t u;
    asm("cvt.rna.tf32.f32 %0, %1;" : "=r"(u) : "f"(x));
    return __uint_as_float(u);
}

__device__ __forceinline__ void mma_tf32(float d[4], const uint32_t a[4], const uint32_t b[2]) {
    asm volatile(
        "mma.sync.aligned.m16n8k8.row.col.f32.tf32.tf32.f32 "
        "{%0,%1,%2,%3}, {%4,%5,%6,%7}, {%8,%9}, {%0,%1,%2,%3};\n"
        : "+f"(d[0]), "+f"(d[1]), "+f"(d[2]), "+f"(d[3])
        : "r"(a[0]), "r"(a[1]), "r"(a[2]), "r"(a[3]),
          "r"(b[0]), "r"(b[1]));
}

// C[M,768] = A[M,768 (lda)] @ B[768,768] (+ bias). M multiple of 128.
// Block tile 128x128, K-tile 16, double-buffered smem, warp tile 64x32
// (2 warps in M x 4 warps in N), 4x4 m16n8k8 TF32 mma per warp per k-step.
__global__ __launch_bounds__(NTHREADS)
void gemm_tf32_kernel(const float* __restrict__ A, int lda,
                      const float* __restrict__ B,
                      const float* __restrict__ bias,
                      float* __restrict__ C)
{
    __shared__ float As[2][BK][BM + 4];   // A stored transposed: As[k][m]
    __shared__ float Bs[2][BK][BN + 4];   // Bs[k][n]

    const int tid  = threadIdx.x;
    const int lane = tid & 31;
    const int warp = tid >> 5;
    const int wm   = warp & 1;    // warp M index (0..1)
    const int wn   = warp >> 1;   // warp N index (0..3)
    const int m0   = blockIdx.y * BM;
    const int n0   = blockIdx.x * BN;

    // global->smem load mapping
    const int a_row = tid >> 2;          // 0..63, second half +64
    const int a_c4  = (tid & 3) * 4;     // k offset (float4)
    const int b_row = tid >> 5;          // 0..7, second half +8
    const int b_c4  = (tid & 31) * 4;    // n offset (float4)

    const float* Aptr = A + (size_t)m0 * lda;
    const float* Bptr = B + n0;

    float acc[4][4][4];
#pragma unroll
    for (int i = 0; i < 4; i++)
#pragma unroll
        for (int j = 0; j < 4; j++)
#pragma unroll
            for (int r = 0; r < 4; r++) acc[i][j][r] = 0.f;

    // preload tile 0
    {
#pragma unroll
        for (int h = 0; h < 2; h++) {
            int r = a_row + h * 64;
            float4 v = *(const float4*)(Aptr + (size_t)r * lda + a_c4);
            As[0][a_c4 + 0][r] = f2tf32(v.x);
            As[0][a_c4 + 1][r] = f2tf32(v.y);
            As[0][a_c4 + 2][r] = f2tf32(v.z);
            As[0][a_c4 + 3][r] = f2tf32(v.w);
        }
#pragma unroll
        for (int h = 0; h < 2; h++) {
            int r = b_row + h * 8;
            float4 v = *(const float4*)(Bptr + (size_t)r * CDIM + b_c4);
            v.x = f2tf32(v.x); v.y = f2tf32(v.y);
            v.z = f2tf32(v.z); v.w = f2tf32(v.w);
            *(float4*)&Bs[0][r][b_c4] = v;
        }
    }
    __syncthreads();

    const int nTiles = CDIM / BK;  // 48
    int cur = 0;
    for (int t = 0; t < nTiles; t++) {
        float4 av[2], bv[2];
        if (t + 1 < nTiles) {
            const int k0 = (t + 1) * BK;
#pragma unroll
            for (int h = 0; h < 2; h++) {
                int r = a_row + h * 64;
                av[h] = *(const float4*)(Aptr + (size_t)r * lda + k0 + a_c4);
            }
#pragma unroll
            for (int h = 0; h < 2; h++) {
                int r = b_row + h * 8;
                bv[h] = *(const float4*)(Bptr + (size_t)(k0 + r) * CDIM + b_c4);
            }
        }

        // compute current tile: 2 k-steps of 8
#pragma unroll
        for (int kk = 0; kk < 2; kk++) {
            uint32_t af[4][4], bf[4][2];
            const int kb = kk * 8 + (lane & 3);
#pragma unroll
            for (int m = 0; m < 4; m++) {
                int r = wm * 64 + m * 16 + (lane >> 2);
                af[m][0] = __float_as_uint(As[cur][kb][r]);
                af[m][1] = __float_as_uint(As[cur][kb][r + 8]);
                af[m][2] = __float_as_uint(As[cur][kb + 4][r]);
                af[m][3] = __float_as_uint(As[cur][kb + 4][r + 8]);
            }
#pragma unroll
            for (int n = 0; n < 4; n++) {
                int c = wn * 32 + n * 8 + (lane >> 2);
                bf[n][0] = __float_as_uint(Bs[cur][kb][c]);
                bf[n][1] = __float_as_uint(Bs[cur][kb + 4][c]);
            }
#pragma unroll
            for (int m = 0; m < 4; m++)
#pragma unroll
                for (int n = 0; n < 4; n++)
                    mma_tf32(acc[m][n], af[m], bf[n]);
        }

        // store prefetched tile into other buffer
        if (t + 1 < nTiles) {
            const int nxt = cur ^ 1;
#pragma unroll
            for (int h = 0; h < 2; h++) {
                int r = a_row + h * 64;
                As[nxt][a_c4 + 0][r] = f2tf32(av[h].x);
                As[nxt][a_c4 + 1][r] = f2tf32(av[h].y);
                As[nxt][a_c4 + 2][r] = f2tf32(av[h].z);
                As[nxt][a_c4 + 3][r] = f2tf32(av[h].w);
            }
#pragma unroll
            for (int h = 0; h < 2; h++) {
                int r = b_row + h * 8;
                float4 v = bv[h];
                v.x = f2tf32(v.x); v.y = f2tf32(v.y);
                v.z = f2tf32(v.z); v.w = f2tf32(v.w);
                *(float4*)&Bs[nxt][r][b_c4] = v;
            }
            cur = nxt;
            __syncthreads();
        }
    }

    // epilogue: D fragment layout of m16n8k8
#pragma unroll
    for (int m = 0; m < 4; m++) {
        int r = m0 + wm * 64 + m * 16 + (lane >> 2);
#pragma unroll
        for (int n = 0; n < 4; n++) {
            int c = n0 + wn * 32 + n * 8 + ((lane & 3) << 1);
            float b0 = bias ? bias[c]     : 0.f;
            float b1 = bias ? bias[c + 1] : 0.f;
            C[(size_t)r * CDIM + c]           = acc[m][n][0] + b0;
            C[(size_t)r * CDIM + c + 1]       = acc[m][n][1] + b1;
            C[(size_t)(r + 8) * CDIM + c]     = acc[m][n][2] + b0;
            C[(size_t)(r + 8) * CDIM + c + 1] = acc[m][n][3] + b1;
        }
    }
}

// b_comb[j] = sum_k b_qkv[2C+k] * W_out[k,j] + b_out[j]
__global__ void bias_kernel(const float* __restrict__ b_qkv,
                            const float* __restrict__ W_out,
                            const float* __restrict__ b_out)
{
    int j = blockIdx.x * blockDim.x + threadIdx.x;
    if (j < CDIM) {
        float s = b_out[j];
#pragma unroll 4
        for (int k = 0; k < CDIM; k++)
            s += b_qkv[2 * CDIM + k] * W_out[(size_t)k * CDIM + j];
        g_bc[j] = s;
    }
}

extern "C" void kernel_launch(void* const* d_in, const int* in_sizes, int n_in,
                              void* d_out, int out_size)
{
    const float* x     = (const float*)d_in[0];
    const float* W_qkv = (const float*)d_in[1];
    const float* b_qkv = (const float*)d_in[2];
    const float* W_out = (const float*)d_in[3];
    const float* b_out = (const float*)d_in[4];
    float* out = (float*)d_out;

    float *Wc = nullptr, *bc = nullptr;
    cudaGetSymbolAddress((void**)&Wc, g_Wc);
    cudaGetSymbolAddress((void**)&bc, g_bc);

    const int M = in_sizes[0] / CDIM;  // B*N = 32768

    // 1) W_comb = W_v @ W_out   (W_v = W_qkv[:, 2C:3C], row stride 3C)
    gemm_tf32_kernel<<<dim3(CDIM / BN, CDIM / BM), NTHREADS>>>(
        W_qkv + 2 * CDIM, 3 * CDIM, W_out, nullptr, Wc);

    // 2) b_comb = b_v @ W_out + b_out
    bias_kernel<<<3, 256>>>(b_qkv, W_out, b_out);

    // 3) out = x @ W_comb + b_comb
    gemm_tf32_kernel<<<dim3(CDIM / BN, M / BM), NTHREADS>>>(
        x, CDIM, Wc, bc, out);
}

// round 4
// speedup vs baseline: 1.0521x; 1.0521x over previous
#include <cuda_runtime.h>
#include <stdint.h>

// out = x @ (W_v @ W_out) + (b_v @ W_out + b_out)   [eye-mask => softmax == identity routing]
// sm_100 baseline target: no tcgen05 / wgmma. Optimized sm_80-style TF32 mma.sync:
//  - swizzled SMEM (stride=+8 pad + k-dependent m-rotation) => conflict-free STS and frag LDS
//  - BM=128 x BN=256, 512 threads (16 warps), warp tile 32x64, double-buffered tiles.

#define CDIM 768
#define BM 128
#define BN 256
#define BK 16
#define MAIN_THREADS 512
#define A_STRIDE (BM + 8)     // 136 floats, stride % 32 == 8
#define B_STRIDE (BN + 8)     // 264 floats
#define A_BUF_FLOATS (BK * A_STRIDE)   // 2176
#define B_BUF_FLOATS (BK * B_STRIDE)   // 4224
#define SMEM_FLOATS (2 * A_BUF_FLOATS + 2 * B_BUF_FLOATS)  // 12800 floats = 51200 B

__device__ float g_WcT[CDIM * CDIM];   // (W_v @ W_out)^T, tf32-rounded, K-major
__device__ float g_bc[CDIM];

__device__ __forceinline__ float f2tf32(float x) {
    uint32_t u;
    asm("cvt.rna.tf32.f32 %0, %1;" : "=r"(u) : "f"(x));
    return __uint_as_float(u);
}

__device__ __forceinline__ void mma_tf32_frag(float d[4], const uint32_t a[4], const uint32_t b[2]) {
    asm volatile(
        "mma.sync.aligned.m16n8k8.row.col.f32.tf32.tf32.f32 "
        "{%0,%1,%2,%3}, {%4,%5,%6,%7}, {%8,%9}, {%0,%1,%2,%3};\n"
        : "+f"(d[0]), "+f"(d[1]), "+f"(d[2]), "+f"(d[3])
        : "r"(a[0]), "r"(a[1]), "r"(a[2]), "r"(a[3]), "r"(b[0]), "r"(b[1]));
}

// ---------------- main GEMM: C[M,768] = A[M,768] @ WcT^T + bias ----------------
// D[m][n] = sum_k A[m][k]*B[n][k];  B = g_WcT (tf32-rounded).
// SMEM layout: As[buf][k][m'] with m' = (m + 8*((k>>2)&3)) & 127  (same rotation for B, &255).
__global__ __launch_bounds__(MAIN_THREADS, 1)
void main_gemm(const float* __restrict__ A, const float* __restrict__ B,
               const float* __restrict__ bias, float* __restrict__ C)
{
    extern __shared__ float smem[];
    float* As = smem;                       // [2][BK][A_STRIDE]
    float* Bs = smem + 2 * A_BUF_FLOATS;    // [2][BK][B_STRIDE]

    const int tid  = threadIdx.x;
    const int lane = tid & 31;
    const int wid  = tid >> 5;              // 0..15
    const int wm   = wid & 3;               // M: 4 warps of 32 rows
    const int wn   = wid >> 2;              // N: 4 warps of 64 cols
    const int m0   = blockIdx.y * BM;
    const int n0   = blockIdx.x * BN;

    // global->smem mapping: 1 float4 of A, 2 float4 of B per thread per tile
    const int a_row = tid >> 2;             // 0..127
    const int q4    = (tid & 3) * 4;        // k offset of the float4
    const int sw    = 8 * (tid & 3);        // m-rotation for all 4 k's of this float4

    const float* Aptr = A + (size_t)m0 * CDIM;
    const float* Bptr = B + (size_t)n0 * CDIM;

    float acc[2][8][4];
#pragma unroll
    for (int m = 0; m < 2; m++)
#pragma unroll
        for (int n = 0; n < 8; n++)
#pragma unroll
            for (int r = 0; r < 4; r++) acc[m][n][r] = 0.f;

    // ---- preload tile 0 ----
    {
        float4 va = *(const float4*)(Aptr + (size_t)a_row * CDIM + q4);
        float* a0 = As + 0;
        a0[(q4 + 0) * A_STRIDE + ((a_row + sw) & 127)] = f2tf32(va.x);
        a0[(q4 + 1) * A_STRIDE + ((a_row + sw) & 127)] = f2tf32(va.y);
        a0[(q4 + 2) * A_STRIDE + ((a_row + sw) & 127)] = f2tf32(va.z);
        a0[(q4 + 3) * A_STRIDE + ((a_row + sw) & 127)] = f2tf32(va.w);
#pragma unroll
        for (int i = 0; i < 2; i++) {
            int idx = tid + MAIN_THREADS * i;
            int brow = idx >> 2;
            float4 vb = *(const float4*)(Bptr + (size_t)brow * CDIM + q4);
            float* b0 = Bs + 0;
            b0[(q4 + 0) * B_STRIDE + ((brow + sw) & 255)] = vb.x;
            b0[(q4 + 1) * B_STRIDE + ((brow + sw) & 255)] = vb.y;
            b0[(q4 + 2) * B_STRIDE + ((brow + sw) & 255)] = vb.z;
            b0[(q4 + 3) * B_STRIDE + ((brow + sw) & 255)] = vb.w;
        }
    }
    __syncthreads();

    const int nTiles = CDIM / BK;   // 48
    const int l3 = lane & 3, lr = lane >> 2;

    for (int t = 0; t < nTiles; t++) {
        float4 va, vb0, vb1;
        if (t + 1 < nTiles) {
            const int k0 = (t + 1) * BK;
            va  = *(const float4*)(Aptr + (size_t)a_row * CDIM + k0 + q4);
            vb0 = *(const float4*)(Bptr + (size_t)(tid >> 2) * CDIM + k0 + q4);
            vb1 = *(const float4*)(Bptr + (size_t)((tid + MAIN_THREADS) >> 2) * CDIM + k0 + q4);
        }

        const float* Ac = As + (t & 1) * A_BUF_FLOATS;
        const float* Bc = Bs + (t & 1) * B_BUF_FLOATS;

#pragma unroll
        for (int kk = 0; kk < 2; kk++) {
            const int kb = kk * 8 + l3;
            const int s0 = kk * 16;        // rotation for k in [kk*8, kk*8+4)
            const int s1 = kk * 16 + 8;    // rotation for k in [kk*8+4, kk*8+8)
            uint32_t af[2][4], bf[8][2];
#pragma unroll
            for (int m = 0; m < 2; m++) {
                const int r = wm * 32 + m * 16 + lr;
                af[m][0] = __float_as_uint(Ac[kb * A_STRIDE + ((r + s0) & 127)]);
                af[m][1] = __float_as_uint(Ac[kb * A_STRIDE + ((r + 8 + s0) & 127)]);
                af[m][2] = __float_as_uint(Ac[(kb + 4) * A_STRIDE + ((r + s1) & 127)]);
                af[m][3] = __float_as_uint(Ac[(kb + 4) * A_STRIDE + ((r + 8 + s1) & 127)]);
            }
#pragma unroll
            for (int n = 0; n < 8; n++) {
                const int c = wn * 64 + n * 8 + lr;
                bf[n][0] = __float_as_uint(Bc[kb * B_STRIDE + ((c + s0) & 255)]);
                bf[n][1] = __float_as_uint(Bc[(kb + 4) * B_STRIDE + ((c + s1) & 255)]);
            }
#pragma unroll
            for (int m = 0; m < 2; m++)
#pragma unroll
                for (int n = 0; n < 8; n++)
                    mma_tf32_frag(acc[m][n], af[m], bf[n]);
        }

        if (t + 1 < nTiles) {
            float* An = As + ((t + 1) & 1) * A_BUF_FLOATS;
            float* Bn = Bs + ((t + 1) & 1) * B_BUF_FLOATS;
            An[(q4 + 0) * A_STRIDE + ((a_row + sw) & 127)] = f2tf32(va.x);
            An[(q4 + 1) * A_STRIDE + ((a_row + sw) & 127)] = f2tf32(va.y);
            An[(q4 + 2) * A_STRIDE + ((a_row + sw) & 127)] = f2tf32(va.z);
            An[(q4 + 3) * A_STRIDE + ((a_row + sw) & 127)] = f2tf32(va.w);
            {
                int brow = tid >> 2;
                Bn[(q4 + 0) * B_STRIDE + ((brow + sw) & 255)] = vb0.x;
                Bn[(q4 + 1) * B_STRIDE + ((brow + sw) & 255)] = vb0.y;
                Bn[(q4 + 2) * B_STRIDE + ((brow + sw) & 255)] = vb0.z;
                Bn[(q4 + 3) * B_STRIDE + ((brow + sw) & 255)] = vb0.w;
                brow = (tid + MAIN_THREADS) >> 2;
                Bn[(q4 + 0) * B_STRIDE + ((brow + sw) & 255)] = vb1.x;
                Bn[(q4 + 1) * B_STRIDE + ((brow + sw) & 255)] = vb1.y;
                Bn[(q4 + 2) * B_STRIDE + ((brow + sw) & 255)] = vb1.z;
                Bn[(q4 + 3) * B_STRIDE + ((brow + sw) & 255)] = vb1.w;
            }
            __syncthreads();
        }
    }

    // ---- epilogue ----
#pragma unroll
    for (int m = 0; m < 2; m++) {
        const int r = m0 + wm * 32 + m * 16 + lr;
#pragma unroll
        for (int n = 0; n < 8; n++) {
            const int c = n0 + wn * 64 + n * 8 + (l3 << 1);
            const float b0 = bias[c], b1 = bias[c + 1];
            C[(size_t)r * CDIM + c]           = acc[m][n][0] + b0;
            C[(size_t)r * CDIM + c + 1]       = acc[m][n][1] + b1;
            C[(size_t)(r + 8) * CDIM + c]     = acc[m][n][2] + b0;
            C[(size_t)(r + 8) * CDIM + c + 1] = acc[m][n][3] + b1;
        }
    }
}

// ---------------- prep: WcT[n][k] = tf32( (W_v @ W_out)[k][n] ) ----------------
__global__ __launch_bounds__(128)
void prep_gemm(const float* __restrict__ A, int lda,   // A = W_v (row-major, stride lda)
               const float* __restrict__ B,            // B = W_out [k][n] row-major
               float* __restrict__ CT)                 // CT[n][k]
{
    __shared__ float As[2][16][72];   // As[k][m], stride 72 % 32 == 8
    __shared__ float Bs[2][16][72];   // Bs[k][n]
    const int tid = threadIdx.x, lane = tid & 31, warp = tid >> 5;
    const int wm = warp & 1, wn = warp >> 1;
    const int m0 = blockIdx.y * 64, n0 = blockIdx.x * 64;

    float acc[2][4][4];
#pragma unroll
    for (int i = 0; i < 2; i++)
#pragma unroll
        for (int j = 0; j < 4; j++)
#pragma unroll
            for (int r = 0; r < 4; r++) acc[i][j][r] = 0.f;

#pragma unroll
    for (int h = 0; h < 2; h++) {
        int idx = tid + 128 * h;
        int row = idx >> 2, q = (idx & 3) * 4;
        float4 v = *(const float4*)(A + (size_t)(m0 + row) * lda + q);
        As[0][q + 0][row] = f2tf32(v.x);
        As[0][q + 1][row] = f2tf32(v.y);
        As[0][q + 2][row] = f2tf32(v.z);
        As[0][q + 3][row] = f2tf32(v.w);
    }
#pragma unroll
    for (int h = 0; h < 2; h++) {
        int idx = tid + 128 * h;
        int k = idx >> 4, nq = (idx & 15) * 4;
        float4 v = *(const float4*)(B + (size_t)k * CDIM + n0 + nq);
        Bs[0][k][nq + 0] = f2tf32(v.x);
        Bs[0][k][nq + 1] = f2tf32(v.y);
        Bs[0][k][nq + 2] = f2tf32(v.z);
        Bs[0][k][nq + 3] = f2tf32(v.w);
    }
    __syncthreads();

    const int nT = CDIM / 16;  // 48
    int cur = 0;
    for (int t = 0; t < nT; t++) {
        float4 av[2], bv[2];
        if (t + 1 < nT) {
            const int k0 = (t + 1) * 16;
#pragma unroll
            for (int h = 0; h < 2; h++) {
                int idx = tid + 128 * h;
                int row = idx >> 2, q = (idx & 3) * 4;
                av[h] = *(const float4*)(A + (size_t)(m0 + row) * lda + k0 + q);
            }
#pragma unroll
            for (int h = 0; h < 2; h++) {
                int idx = tid + 128 * h;
                int k = idx >> 4, nq = (idx & 15) * 4;
                bv[h] = *(const float4*)(B + (size_t)(k0 + k) * CDIM + n0 + nq);
            }
        }

#pragma unroll
        for (int kk = 0; kk < 2; kk++) {
            const int kb = kk * 8 + (lane & 3);
            uint32_t af[2][4], bf[4][2];
#pragma unroll
            for (int mf = 0; mf < 2; mf++) {
                int r = wm * 32 + mf * 16 + (lane >> 2);
                af[mf][0] = __float_as_uint(As[cur][kb][r]);
                af[mf][1] = __float_as_uint(As[cur][kb][r + 8]);
                af[mf][2] = __float_as_uint(As[cur][kb + 4][r]);
                af[mf][3] = __float_as_uint(As[cur][kb + 4][r + 8]);
            }
#pragma unroll
            for (int nf = 0; nf < 4; nf++) {
                int c = wn * 32 + nf * 8 + (lane >> 2);
                bf[nf][0] = __float_as_uint(Bs[cur][kb][c]);
                bf[nf][1] = __float_as_uint(Bs[cur][kb + 4][c]);
            }
#pragma unroll
            for (int mf = 0; mf < 2; mf++)
#pragma unroll
                for (int nf = 0; nf < 4; nf++)
                    mma_tf32_frag(acc[mf][nf], af[mf], bf[nf]);
        }

        if (t + 1 < nT) {
            const int nxt = cur ^ 1;
            __syncthreads();
#pragma unroll
            for (int h = 0; h < 2; h++) {
                int idx = tid + 128 * h;
                int row = idx >> 2, q = (idx & 3) * 4;
                As[nxt][q + 0][row] = f2tf32(av[h].x);
                As[nxt][q + 1][row] = f2tf32(av[h].y);
                As[nxt][q + 2][row] = f2tf32(av[h].z);
                As[nxt][q + 3][row] = f2tf32(av[h].w);
            }
#pragma unroll
            for (int h = 0; h < 2; h++) {
                int idx = tid + 128 * h;
                int k = idx >> 4, nq = (idx & 15) * 4;
                Bs[nxt][k][nq + 0] = f2tf32(bv[h].x);
                Bs[nxt][k][nq + 1] = f2tf32(bv[h].y);
                Bs[nxt][k][nq + 2] = f2tf32(bv[h].z);
                Bs[nxt][k][nq + 3] = f2tf32(bv[h].w);
            }
            cur = nxt;
            __syncthreads();
        }
    }

    // write transposed + rna-rounded
#pragma unroll
    for (int mf = 0; mf < 2; mf++) {
        int r = m0 + wm * 32 + mf * 16 + (lane >> 2);
#pragma unroll
        for (int nf = 0; nf < 4; nf++) {
            int c = n0 + wn * 32 + nf * 8 + ((lane & 3) << 1);
            CT[(size_t)c * CDIM + r]           = f2tf32(acc[mf][nf][0]);
            CT[(size_t)(c + 1) * CDIM + r]     = f2tf32(acc[mf][nf][1]);
            CT[(size_t)c * CDIM + r + 8]       = f2tf32(acc[mf][nf][2]);
            CT[(size_t)(c + 1) * CDIM + r + 8] = f2tf32(acc[mf][nf][3]);
        }
    }
}

// b_comb[j] = sum_k b_qkv[2C+k] * W_out[k,j] + b_out[j]
__global__ void bias_kernel(const float* __restrict__ b_qkv,
                            const float* __restrict__ W_out,
                            const float* __restrict__ b_out)
{
    int j = blockIdx.x * blockDim.x + threadIdx.x;
    if (j < CDIM) {
        float s = b_out[j];
#pragma unroll 4
        for (int k = 0; k < CDIM; k++)
            s += b_qkv[2 * CDIM + k] * W_out[(size_t)k * CDIM + j];
        g_bc[j] = s;
    }
}

extern "C" void kernel_launch(void* const* d_in, const int* in_sizes, int n_in,
                              void* d_out, int out_size)
{
    const float* x     = (const float*)d_in[0];
    const float* W_qkv = (const float*)d_in[1];
    const float* b_qkv = (const float*)d_in[2];
    const float* W_out = (const float*)d_in[3];
    const float* b_out = (const float*)d_in[4];
    float* out = (float*)d_out;

    float *WcT = nullptr, *bc = nullptr;
    cudaGetSymbolAddress((void**)&WcT, g_WcT);
    cudaGetSymbolAddress((void**)&bc, g_bc);

    const int M = in_sizes[0] / CDIM;  // 32768

    static int smem_set = 0;
    if (!smem_set) {
        cudaFuncSetAttribute(main_gemm, cudaFuncAttributeMaxDynamicSharedMemorySize,
                             SMEM_FLOATS * 4);
        smem_set = 1;
    }

    // 1) WcT = (W_v @ W_out)^T, tf32-rounded   (W_v = W_qkv[:, 2C:3C], stride 3C)
    prep_gemm<<<dim3(CDIM / 64, CDIM / 64), 128>>>(W_qkv + 2 * CDIM, 3 * CDIM, W_out, WcT);

    // 2) b_comb
    bias_kernel<<<3, 256>>>(b_qkv, W_out, b_out);

    // 3) out = x @ Wc + b_comb
    main_gemm<<<dim3(CDIM / BN, M / BM), MAIN_THREADS, SMEM_FLOATS * 4>>>(x, WcT, bc, out);
}

// round 5
// speedup vs baseline: 1.7516x; 1.6648x over previous
#include <cuda_runtime.h>
#include <cuda_fp16.h>
#include <stdint.h>

// out = x @ (W_v @ W_out) + (b_v @ W_out + b_out)   [eye-mask => softmax == identity routing]
// Legacy-mma path is tensor-PIPE-bound on this target (~90 TF/s tf32 measured, invariant to
// memory optimizations). Switch main GEMM to fp16 m16n8k16 (2x FLOP per HMMA) + ldmatrix.
// Precision: x,Wc rounded to fp16 (rn): predicted rel_err ~5e-4 (threshold 1e-3).

#define CDIM 768
#define BM 128
#define BN 192
#define BK 32
#define NTH 512
#define ASTR 40                         // halves per smem row (80B; ldmatrix conflict-free)
#define ABUF (BM * ASTR)                // 5120 halves
#define BBUF (BN * ASTR)                // 7680 halves
#define STAGE_H (ABUF + BBUF)           // 12800 halves
#define SMEM_BYTES (2 * STAGE_H * 2)    // 51200 B

__device__ __half g_Wch[CDIM * CDIM];   // (W_v @ W_out)^T as fp16, K-major: g_Wch[n*768+k]
__device__ float  g_bc[CDIM];

__device__ __forceinline__ float f2tf32(float x) {
    uint32_t u;
    asm("cvt.rna.tf32.f32 %0, %1;" : "=r"(u) : "f"(x));
    return __uint_as_float(u);
}

__device__ __forceinline__ uint32_t smem_u32(const void* p) {
    return (uint32_t)__cvta_generic_to_shared(p);
}

__device__ __forceinline__ void ldsm4(uint32_t& r0, uint32_t& r1, uint32_t& r2, uint32_t& r3,
                                      uint32_t addr) {
    asm volatile("ldmatrix.sync.aligned.m8n8.x4.shared.b16 {%0,%1,%2,%3}, [%4];"
                 : "=r"(r0), "=r"(r1), "=r"(r2), "=r"(r3) : "r"(addr));
}

__device__ __forceinline__ void mma_f16(float d[4], const uint32_t a[4],
                                        uint32_t b0, uint32_t b1) {
    asm volatile(
        "mma.sync.aligned.m16n8k16.row.col.f32.f16.f16.f32 "
        "{%0,%1,%2,%3}, {%4,%5,%6,%7}, {%8,%9}, {%0,%1,%2,%3};\n"
        : "+f"(d[0]), "+f"(d[1]), "+f"(d[2]), "+f"(d[3])
        : "r"(a[0]), "r"(a[1]), "r"(a[2]), "r"(a[3]), "r"(b0), "r"(b1));
}

__device__ __forceinline__ uint2 f4_to_h4(float4 v) {
    uint2 u;
    __half2 lo = __halves2half2(__float2half_rn(v.x), __float2half_rn(v.y));
    __half2 hi = __halves2half2(__float2half_rn(v.z), __float2half_rn(v.w));
    u.x = *(uint32_t*)&lo;
    u.y = *(uint32_t*)&hi;
    return u;
}

// ---------------- main GEMM: C[M,768] = A[M,768] @ Wch^T + bias ----------------
// D[m][n] = sum_k A[m][k] * B[n][k];  A fp32->fp16 in-kernel, B already fp16.
__global__ __launch_bounds__(NTH, 1)
void main_gemm(const float* __restrict__ A, const __half* __restrict__ B,
               const float* __restrict__ bias, float* __restrict__ C)
{
    extern __shared__ __align__(16) __half sm[];
    __half* As = sm;                    // [2][BM][ASTR]
    __half* Bs = sm + 2 * ABUF;         // [2][BN][ASTR]

    const int tid  = threadIdx.x;
    const int lane = tid & 31;
    const int wid  = tid >> 5;          // 0..15
    const int wm   = wid & 3;           // 4 warps x 32 rows
    const int wn   = wid >> 2;          // 4 warps x 48 cols
    const int m0   = blockIdx.y * BM;
    const int n0   = blockIdx.x * BN;

    const float*  Aptr = A + (size_t)m0 * CDIM;
    const __half* Bptr = B + (size_t)n0 * CDIM;

    // loader mappings
    const int a_row0 = tid >> 3, a_c0 = tid & 7;             // idx = tid      (A chunk 0)
    const int a_row1 = (tid + NTH) >> 3, a_c1 = tid & 7;     // idx = tid+512  (A chunk 1)
    const int b_row0 = tid >> 2, b_c0 = tid & 3;             // B chunk 0
    const int b_idx1 = tid + NTH;                            // B chunk 1 (guarded < 768)
    const int b_row1 = b_idx1 >> 2, b_c1 = b_idx1 & 3;
    const bool b_ok1 = b_idx1 < (BN * 4);

    float acc[2][6][4];
#pragma unroll
    for (int m = 0; m < 2; m++)
#pragma unroll
        for (int n = 0; n < 6; n++)
#pragma unroll
            for (int r = 0; r < 4; r++) acc[m][n][r] = 0.f;

    // ---- preload tile 0 ----
    {
        float4 va0 = *(const float4*)(Aptr + (size_t)a_row0 * CDIM + 4 * a_c0);
        float4 va1 = *(const float4*)(Aptr + (size_t)a_row1 * CDIM + 4 * a_c1);
        *(uint2*)(As + a_row0 * ASTR + 4 * a_c0) = f4_to_h4(va0);
        *(uint2*)(As + a_row1 * ASTR + 4 * a_c1) = f4_to_h4(va1);
        uint4 vb0 = *(const uint4*)(Bptr + (size_t)b_row0 * CDIM + 8 * b_c0);
        *(uint4*)(Bs + b_row0 * ASTR + 8 * b_c0) = vb0;
        if (b_ok1) {
            uint4 vb1 = *(const uint4*)(Bptr + (size_t)b_row1 * CDIM + 8 * b_c1);
            *(uint4*)(Bs + b_row1 * ASTR + 8 * b_c1) = vb1;
        }
    }
    __syncthreads();

    // ldmatrix lane addressing (within a tile buffer)
    const int a_lrow = (lane & 15);
    const int a_lbo  = (lane >> 4) << 4;                     // 0 or 16 bytes (k-lo/k-hi)
    const int b_lrow = (lane & 7) + ((lane >> 4) << 3);      // row within 16-n group
    const int b_lbo  = ((lane >> 3) & 1) << 4;

    const int nTiles = CDIM / BK;   // 24

    for (int t = 0; t < nTiles; t++) {
        float4 va0, va1; uint4 vb0, vb1;
        if (t + 1 < nTiles) {
            const int k0 = (t + 1) * BK;
            va0 = *(const float4*)(Aptr + (size_t)a_row0 * CDIM + k0 + 4 * a_c0);
            va1 = *(const float4*)(Aptr + (size_t)a_row1 * CDIM + k0 + 4 * a_c1);
            vb0 = *(const uint4*)(Bptr + (size_t)b_row0 * CDIM + k0 + 8 * b_c0);
            if (b_ok1)
                vb1 = *(const uint4*)(Bptr + (size_t)b_row1 * CDIM + k0 + 8 * b_c1);
        }

        const uint32_t Ab = smem_u32(As + (t & 1) * ABUF);
        const uint32_t Bb = smem_u32(Bs + (t & 1) * BBUF);

#pragma unroll
        for (int ks = 0; ks < 2; ks++) {
            uint32_t af[2][4], bf[12];
#pragma unroll
            for (int m = 0; m < 2; m++) {
                const int Rb = wm * 32 + m * 16;
                uint32_t addr = Ab + (uint32_t)((Rb + a_lrow) * (ASTR * 2) + 32 * ks + a_lbo);
                ldsm4(af[m][0], af[m][1], af[m][2], af[m][3], addr);
            }
#pragma unroll
            for (int j = 0; j < 3; j++) {
                const int Nb = wn * 48 + 16 * j;
                uint32_t addr = Bb + (uint32_t)((Nb + b_lrow) * (ASTR * 2) + 32 * ks + b_lbo);
                ldsm4(bf[4 * j + 0], bf[4 * j + 1], bf[4 * j + 2], bf[4 * j + 3], addr);
            }
#pragma unroll
            for (int m = 0; m < 2; m++)
#pragma unroll
                for (int n = 0; n < 6; n++) {
                    const int jj = (n >> 1) * 4 + (n & 1) * 2;
                    mma_f16(acc[m][n], af[m], bf[jj], bf[jj + 1]);
                }
        }

        if (t + 1 < nTiles) {
            __half* An = As + ((t + 1) & 1) * ABUF;
            __half* Bn = Bs + ((t + 1) & 1) * BBUF;
            __syncthreads();
            *(uint2*)(An + a_row0 * ASTR + 4 * a_c0) = f4_to_h4(va0);
            *(uint2*)(An + a_row1 * ASTR + 4 * a_c1) = f4_to_h4(va1);
            *(uint4*)(Bn + b_row0 * ASTR + 8 * b_c0) = vb0;
            if (b_ok1) *(uint4*)(Bn + b_row1 * ASTR + 8 * b_c1) = vb1;
            __syncthreads();
        }
    }

    // ---- epilogue ----
    const int l3 = lane & 3, lr = lane >> 2;
#pragma unroll
    for (int m = 0; m < 2; m++) {
        const int r = m0 + wm * 32 + m * 16 + lr;
#pragma unroll
        for (int n = 0; n < 6; n++) {
            const int c = n0 + wn * 48 + n * 8 + (l3 << 1);
            const float b0 = bias[c], b1 = bias[c + 1];
            float2 o0 = {acc[m][n][0] + b0, acc[m][n][1] + b1};
            float2 o1 = {acc[m][n][2] + b0, acc[m][n][3] + b1};
            *(float2*)(C + (size_t)r * CDIM + c)       = o0;
            *(float2*)(C + (size_t)(r + 8) * CDIM + c) = o1;
        }
    }
}

// ---------------- prep: Wch[n][k] = fp16( (W_v @ W_out)[k][n] ), tf32 compute --------------
__device__ __forceinline__ void mma_tf32_frag(float d[4], const uint32_t a[4], const uint32_t b[2]) {
    asm volatile(
        "mma.sync.aligned.m16n8k8.row.col.f32.tf32.tf32.f32 "
        "{%0,%1,%2,%3}, {%4,%5,%6,%7}, {%8,%9}, {%0,%1,%2,%3};\n"
        : "+f"(d[0]), "+f"(d[1]), "+f"(d[2]), "+f"(d[3])
        : "r"(a[0]), "r"(a[1]), "r"(a[2]), "r"(a[3]), "r"(b[0]), "r"(b[1]));
}

__global__ __launch_bounds__(128)
void prep_gemm(const float* __restrict__ A, int lda,   // A = W_v (row-major, stride lda)
               const float* __restrict__ B,            // B = W_out [k][n] row-major
               __half* __restrict__ CT)                // CT[n][k]
{
    __shared__ float As[2][16][72];
    __shared__ float Bs[2][16][72];
    const int tid = threadIdx.x, lane = tid & 31, warp = tid >> 5;
    const int wm = warp & 1, wn = warp >> 1;
    const int m0 = blockIdx.y * 64, n0 = blockIdx.x * 64;

    float acc[2][4][4];
#pragma unroll
    for (int i = 0; i < 2; i++)
#pragma unroll
        for (int j = 0; j < 4; j++)
#pragma unroll
            for (int r = 0; r < 4; r++) acc[i][j][r] = 0.f;

#pragma unroll
    for (int h = 0; h < 2; h++) {
        int idx = tid + 128 * h;
        int row = idx >> 2, q = (idx & 3) * 4;
        float4 v = *(const float4*)(A + (size_t)(m0 + row) * lda + q);
        As[0][q + 0][row] = f2tf32(v.x);
        As[0][q + 1][row] = f2tf32(v.y);
        As[0][q + 2][row] = f2tf32(v.z);
        As[0][q + 3][row] = f2tf32(v.w);
    }
#pragma unroll
    for (int h = 0; h < 2; h++) {
        int idx = tid + 128 * h;
        int k = idx >> 4, nq = (idx & 15) * 4;
        float4 v = *(const float4*)(B + (size_t)k * CDIM + n0 + nq);
        Bs[0][k][nq + 0] = f2tf32(v.x);
        Bs[0][k][nq + 1] = f2tf32(v.y);
        Bs[0][k][nq + 2] = f2tf32(v.z);
        Bs[0][k][nq + 3] = f2tf32(v.w);
    }
    __syncthreads();

    const int nT = CDIM / 16;  // 48
    int cur = 0;
    for (int t = 0; t < nT; t++) {
        float4 av[2], bv[2];
        if (t + 1 < nT) {
            const int k0 = (t + 1) * 16;
#pragma unroll
            for (int h = 0; h < 2; h++) {
                int idx = tid + 128 * h;
                int row = idx >> 2, q = (idx & 3) * 4;
                av[h] = *(const float4*)(A + (size_t)(m0 + row) * lda + k0 + q);
            }
#pragma unroll
            for (int h = 0; h < 2; h++) {
                int idx = tid + 128 * h;
                int k = idx >> 4, nq = (idx & 15) * 4;
                bv[h] = *(const float4*)(B + (size_t)(k0 + k) * CDIM + n0 + nq);
            }
        }

#pragma unroll
        for (int kk = 0; kk < 2; kk++) {
            const int kb = kk * 8 + (lane & 3);
            uint32_t af[2][4], bf[4][2];
#pragma unroll
            for (int mf = 0; mf < 2; mf++) {
                int r = wm * 32 + mf * 16 + (lane >> 2);
                af[mf][0] = __float_as_uint(As[cur][kb][r]);
                af[mf][1] = __float_as_uint(As[cur][kb][r + 8]);
                af[mf][2] = __float_as_uint(As[cur][kb + 4][r]);
                af[mf][3] = __float_as_uint(As[cur][kb + 4][r + 8]);
            }
#pragma unroll
            for (int nf = 0; nf < 4; nf++) {
                int c = wn * 32 + nf * 8 + (lane >> 2);
                bf[nf][0] = __float_as_uint(Bs[cur][kb][c]);
                bf[nf][1] = __float_as_uint(Bs[cur][kb + 4][c]);
            }
#pragma unroll
            for (int mf = 0; mf < 2; mf++)
#pragma unroll
                for (int nf = 0; nf < 4; nf++)
                    mma_tf32_frag(acc[mf][nf], af[mf], bf[nf]);
        }

        if (t + 1 < nT) {
            const int nxt = cur ^ 1;
            __syncthreads();
#pragma unroll
            for (int h = 0; h < 2; h++) {
                int idx = tid + 128 * h;
                int row = idx >> 2, q = (idx & 3) * 4;
                As[nxt][q + 0][row] = f2tf32(av[h].x);
                As[nxt][q + 1][row] = f2tf32(av[h].y);
                As[nxt][q + 2][row] = f2tf32(av[h].z);
                As[nxt][q + 3][row] = f2tf32(av[h].w);
            }
#pragma unroll
            for (int h = 0; h < 2; h++) {
                int idx = tid + 128 * h;
                int k = idx >> 4, nq = (idx & 15) * 4;
                Bs[nxt][k][nq + 0] = f2tf32(bv[h].x);
                Bs[nxt][k][nq + 1] = f2tf32(bv[h].y);
                Bs[nxt][k][nq + 2] = f2tf32(bv[h].z);
                Bs[nxt][k][nq + 3] = f2tf32(bv[h].w);
            }
            cur = nxt;
            __syncthreads();
        }
    }

    // write transposed, rounded to fp16
#pragma unroll
    for (int mf = 0; mf < 2; mf++) {
        int r = m0 + wm * 32 + mf * 16 + (lane >> 2);
#pragma unroll
        for (int nf = 0; nf < 4; nf++) {
            int c = n0 + wn * 32 + nf * 8 + ((lane & 3) << 1);
            CT[(size_t)c * CDIM + r]           = __float2half_rn(acc[mf][nf][0]);
            CT[(size_t)(c + 1) * CDIM + r]     = __float2half_rn(acc[mf][nf][1]);
            CT[(size_t)c * CDIM + r + 8]       = __float2half_rn(acc[mf][nf][2]);
            CT[(size_t)(c + 1) * CDIM + r + 8] = __float2half_rn(acc[mf][nf][3]);
        }
    }
}

// b_comb[j] = sum_k b_qkv[2C+k] * W_out[k,j] + b_out[j]
__global__ void bias_kernel(const float* __restrict__ b_qkv,
                            const float* __restrict__ W_out,
                            const float* __restrict__ b_out)
{
    int j = blockIdx.x * blockDim.x + threadIdx.x;
    if (j < CDIM) {
        float s = b_out[j];
#pragma unroll 4
        for (int k = 0; k < CDIM; k++)
            s += b_qkv[2 * CDIM + k] * W_out[(size_t)k * CDIM + j];
        g_bc[j] = s;
    }
}

extern "C" void kernel_launch(void* const* d_in, const int* in_sizes, int n_in,
                              void* d_out, int out_size)
{
    const float* x     = (const float*)d_in[0];
    const float* W_qkv = (const float*)d_in[1];
    const float* b_qkv = (const float*)d_in[2];
    const float* W_out = (const float*)d_in[3];
    const float* b_out = (const float*)d_in[4];
    float* out = (float*)d_out;

    __half* Wch = nullptr; float* bc = nullptr;
    cudaGetSymbolAddress((void**)&Wch, g_Wch);
    cudaGetSymbolAddress((void**)&bc, g_bc);

    const int M = in_sizes[0] / CDIM;  // 32768

    static int smem_set = 0;
    if (!smem_set) {
        cudaFuncSetAttribute(main_gemm, cudaFuncAttributeMaxDynamicSharedMemorySize, SMEM_BYTES);
        smem_set = 1;
    }

    // 1) Wch = fp16((W_v @ W_out)^T)   (W_v = W_qkv[:, 2C:3C], stride 3C)
    prep_gemm<<<dim3(CDIM / 64, CDIM / 64), 128>>>(W_qkv + 2 * CDIM, 3 * CDIM, W_out, Wch);

    // 2) b_comb
    bias_kernel<<<3, 256>>>(b_qkv, W_out, b_out);

    // 3) out = x @ Wc + b_comb   (fp16 tensor cores)
    main_gemm<<<dim3(CDIM / BN, M / BM), NTH, SMEM_BYTES>>>(x, Wch, bc, out);
}